// round 4
// baseline (speedup 1.0000x reference)
#include <cuda_runtime.h>
#include <cuda_bf16.h>
#include <cstdint>

#define NF 4096
#define D 128
#define NBINS 101
#define NB2 (2 * NBINS)
#define TILE 128
#define THREADS 256
#define NHCOPY 4
#define QSCALE 262144.0f           // 2^18
#define QMASK ((1ULL << 40) - 1ULL)
#define TSTRIDE 136                // bf16 elements per smem tile row (128 + 8 pad)
#define TROWB (TSTRIDE * 2)        // 272 bytes = 17 * 16B -> conflict-free LDSM
#define TILE_BYTES (TILE * TROWB)  // 34816

__device__ float g_cnt[NB2];
__device__ float g_frc[NB2];
__device__ int g_is64;
__device__ __align__(16) __nv_bfloat16 g_hi[NF * D];
__device__ __align__(16) __nv_bfloat16 g_lo[NF * D];

__device__ __forceinline__ uint32_t smem_to_u32(const void* p) {
    uint32_t a;
    asm("{ .reg .u64 t; cvta.to.shared.u64 t, %1; cvt.u32.u64 %0, t; }" : "=r"(a) : "l"(p));
    return a;
}

#define LDSM_X4(r, a) \
    asm volatile("ldmatrix.sync.aligned.m8n8.x4.shared.b16 {%0,%1,%2,%3}, [%4];" \
                 : "=r"((r)[0]), "=r"((r)[1]), "=r"((r)[2]), "=r"((r)[3]) : "r"(a))
#define LDSM_X2(r, a) \
    asm volatile("ldmatrix.sync.aligned.m8n8.x2.shared.b16 {%0,%1}, [%2];" \
                 : "=r"((r)[0]), "=r"((r)[1]) : "r"(a))
#define MMA16816(d, a, b) \
    asm volatile("mma.sync.aligned.m16n8k16.row.col.f32.bf16.bf16.f32 " \
                 "{%0,%1,%2,%3}, {%4,%5,%6,%7}, {%8,%9}, {%0,%1,%2,%3};" \
                 : "+f"((d)[0]), "+f"((d)[1]), "+f"((d)[2]), "+f"((d)[3]) \
                 : "r"((a)[0]), "r"((a)[1]), "r"((a)[2]), "r"((a)[3]), \
                   "r"((b)[0]), "r"((b)[1]))
#define STS128(sa, v) \
    asm volatile("st.shared.v4.b32 [%0], {%1,%2,%3,%4};" \
                 :: "r"(sa), "r"((v).x), "r"((v).y), "r"((v).z), "r"((v).w) : "memory")

// -------------------------------------------------------------------------
// prep: split F into bf16 hi/lo, zero hist accumulators, sniff class dtype
__global__ void prep_kernel(const float* __restrict__ F, const int* __restrict__ cls32) {
    int gid = blockIdx.x * blockDim.x + threadIdx.x;
    for (int i = gid; i < NF * D; i += gridDim.x * blockDim.x) {
        float a = F[i];
        __nv_bfloat16 hi = __float2bfloat16(a);
        __nv_bfloat16 lo = __float2bfloat16(a - __bfloat162float(hi));
        g_hi[i] = hi;
        g_lo[i] = lo;
    }
    if (blockIdx.x == 0) {
        int t = threadIdx.x;
        if (t < NB2) { g_cnt[t] = 0.0f; g_frc[t] = 0.0f; }
        if (t < 32) {
            int v = cls32[2 * t + 1];    // int64 LE: odd words are 0 (classes 0..31)
            unsigned bal = __ballot_sync(0xffffffffu, v != 0);
            if (t == 0) g_is64 = (bal == 0) ? 1 : 0;
        }
    }
}

// Fill one 128x128 bf16 tile into padded smem (row stride TSTRIDE bf16).
__device__ __forceinline__ void fill_tile(uint32_t tile_base, const __nv_bfloat16* __restrict__ src,
                                          int row0, int t) {
#pragma unroll
    for (int it = 0; it < 8; it++) {
        int idx = it * THREADS + t;          // 0..2047 uint4 slots
        int r = idx >> 4;                    // row 0..127
        int c8 = idx & 15;                   // 8-bf16 group
        uint4 v = *reinterpret_cast<const uint4*>(src + (size_t)(row0 + r) * D + c8 * 8);
        STS128(tile_base + (uint32_t)(r * TROWB + c8 * 16), v);
    }
}

__global__ __launch_bounds__(THREADS, 1)
void pair_hist_kernel(const void* __restrict__ cls_raw) {
    const int bj = blockIdx.x;
    const int bi = blockIdx.y;
    if (bj < bi) return;

    extern __shared__ char dsm[];
    __shared__ unsigned long long whist[NHCOPY][NB2];
    __shared__ int clsA[TILE], clsB[TILE];

    const int t    = threadIdx.x;
    const int wid  = t >> 5;
    const int lane = t & 31;
    const int wr   = wid >> 2;    // warp row 0..1  (64 rows each)
    const int wc   = wid & 3;     // warp col 0..3  (32 cols each)

    uint32_t base = smem_to_u32(dsm);
    const uint32_t AH = base, AL = base + TILE_BYTES, BH = base + 2 * TILE_BYTES,
                   BL = base + 3 * TILE_BYTES;

    for (int i = t; i < NHCOPY * NB2; i += THREADS) (&whist[0][0])[i] = 0ULL;

    if (t < TILE) {
        int va, vb;
        if (g_is64) {
            const long long* c = (const long long*)cls_raw;
            va = (int)c[bi * TILE + t];
            vb = (int)c[bj * TILE + t];
        } else {
            const int* c = (const int*)cls_raw;
            va = c[bi * TILE + t];
            vb = c[bj * TILE + t];
        }
        clsA[t] = va; clsB[t] = vb;
    }

    fill_tile(AH, g_hi, bi * TILE, t);
    fill_tile(AL, g_lo, bi * TILE, t);
    fill_tile(BH, g_hi, bj * TILE, t);
    fill_tile(BL, g_lo, bj * TILE, t);
    __syncthreads();

    // per-thread ldmatrix base offsets (k-step 0)
    // A (x4): row = warp_row_base + mtile*16 + (lane&15), col = 8*(lane>>4)
    // B (x2): row = warp_col_base + ntile*8  + (lane&7),  col = 8*((lane>>3)&1)
    uint32_t aoff[4], boff[4];
#pragma unroll
    for (int m = 0; m < 4; m++)
        aoff[m] = (uint32_t)((wr * 64 + m * 16 + (lane & 15)) * TROWB + (lane >> 4) * 16);
#pragma unroll
    for (int n = 0; n < 4; n++)
        boff[n] = (uint32_t)((wc * 32 + n * 8 + (lane & 7)) * TROWB + ((lane >> 3) & 1) * 16);

    float acc[4][4][4];
#pragma unroll
    for (int m = 0; m < 4; m++)
#pragma unroll
        for (int n = 0; n < 4; n++)
#pragma unroll
            for (int e = 0; e < 4; e++) acc[m][n][e] = 0.0f;

#pragma unroll
    for (int ks = 0; ks < 8; ks++) {
        const uint32_t kb = ks * 32;   // 16 bf16 = 32 bytes per k-step
        uint32_t ah[4][4], al[4][4], bh[4][2], bl[4][2];
#pragma unroll
        for (int m = 0; m < 4; m++) {
            LDSM_X4(ah[m], AH + aoff[m] + kb);
            LDSM_X4(al[m], AL + aoff[m] + kb);
        }
#pragma unroll
        for (int n = 0; n < 4; n++) {
            LDSM_X2(bh[n], BH + boff[n] + kb);
            LDSM_X2(bl[n], BL + boff[n] + kb);
        }
#pragma unroll
        for (int m = 0; m < 4; m++)
#pragma unroll
            for (int n = 0; n < 4; n++) {
                MMA16816(acc[m][n], ah[m], bh[n]);
                MMA16816(acc[m][n], ah[m], bl[n]);
                MMA16816(acc[m][n], al[m], bh[n]);
            }
    }

    // ---- warp-aggregated binning straight from register accumulators ----
    unsigned long long* hw = whist[wid & (NHCOPY - 1)];
    const bool diag = (bi == bj);
#pragma unroll
    for (int m = 0; m < 4; m++) {
#pragma unroll
        for (int n = 0; n < 4; n++) {
#pragma unroll
            for (int e = 0; e < 4; e++) {
                const int il = wr * 64 + m * 16 + (lane >> 2) + ((e >> 1) << 3);
                const int jl = wc * 32 + n * 8 + ((lane & 3) << 1) + (e & 1);
                const bool valid = !(diag && jl <= il);
                float s = acc[m][n][e];
                float posf = fmaf(s, 50.0f, 50.0f);   // (s+1)/step, step = 2/100
                int idx = (int)floorf(posf);
                idx = max(0, min(idx, NBINS - 1));
                float frac = posf - (float)idx;
                frac = fminf(fmaxf(frac, 0.0f), 1.0f);
                int key = idx + ((clsA[il] == clsB[jl]) ? 0 : NBINS);
                unsigned q = __float2uint_rn(frac * QSCALE);
                unsigned act = __ballot_sync(0xffffffffu, valid);
                if (valid) {
                    unsigned grp = __match_any_sync(act, key);
                    unsigned qs  = __reduce_add_sync(grp, q);
                    if (lane == __ffs(grp) - 1) {
                        unsigned long long v =
                            ((unsigned long long)__popc(grp) << 40) | (unsigned long long)qs;
                        atomicAdd(&hw[key], v);
                    }
                }
            }
        }
    }

    __syncthreads();
    for (int i = t; i < NB2; i += THREADS) {
        unsigned long long s = 0ULL;
#pragma unroll
        for (int w = 0; w < NHCOPY; w++) s += whist[w][i];
        if (s != 0ULL) {
            atomicAdd(&g_cnt[i], (float)(unsigned)(s >> 40));
            atomicAdd(&g_frc[i], (float)(unsigned long long)(s & QMASK) * (1.0f / QSCALE));
        }
    }
}

// -------------------------------------------------------------------------
__global__ void finalize_kernel(float* out) {
    __shared__ float hp[NBINS], hn[NBINS];
    int t = threadIdx.x;
    if (t < NB2) {
        int b = (t < NBINS) ? t : (t - NBINS);
        float h = g_cnt[t];
        if (b < NBINS - 1) h -= g_frc[t];
        if (b > 0)         h += g_frc[t - 1];
        if (t < NBINS) hp[b] = h; else hn[b] = h;
    }
    __syncthreads();
    if (t == 0) {
        double Sp = 0.0, Sn = 0.0;
#pragma unroll 4
        for (int i = 0; i < NBINS; i++) { Sp += (double)hp[i]; Sn += (double)hn[i]; }
        if (Sp <= 0.0) Sp = 1.0;
        if (Sn <= 0.0) Sn = 1.0;
        double cdf = 0.0, loss = 0.0;
#pragma unroll 4
        for (int j = 0; j < NBINS; j++) {
            cdf  += (double)hp[j];
            loss += (double)hn[j] * cdf;
        }
        out[0] = (float)(loss / (Sp * Sn));
    }
}

__global__ void dummy_kernel() {}   // pads launch cycle to 4 so ncu (-s 5 -c 1) hits pair kernel

extern "C" void kernel_launch(void* const* d_in, const int* in_sizes, int n_in,
                              void* d_out, int out_size) {
    const float* F  = (const float*)d_in[0];
    const void* cls = d_in[1];
    (void)in_sizes; (void)n_in; (void)out_size;

    const int DSMEM = 4 * TILE_BYTES;   // 139264 bytes
    cudaFuncSetAttribute(pair_hist_kernel, cudaFuncAttributeMaxDynamicSharedMemorySize, DSMEM);

    prep_kernel<<<2048, 256>>>(F, (const int*)cls);
    dim3 grid(NF / TILE, NF / TILE);
    pair_hist_kernel<<<grid, THREADS, DSMEM>>>(cls);
    finalize_kernel<<<1, 256>>>((float*)d_out);
    dummy_kernel<<<1, 32>>>();
}

// round 7
// speedup vs baseline: 1.4940x; 1.4940x over previous
#include <cuda_runtime.h>
#include <cstdint>

#define NF 4096
#define D 128
#define NBINS 101
#define NB2 (2 * NBINS)
#define TM 128            // CTA tile rows
#define TN 64             // CTA tile cols
#define KC 32
#define KST 34            // smem row stride in floats (pad 2): conflict-free LDS.64
#define THREADS 256
#define NHCOPY 4
#define QSCALE 262144.0f
#define QMASK ((1ULL << 40) - 1ULL)

__device__ float g_cnt[NB2];
__device__ float g_frc[NB2];
__device__ int g_is64;

__device__ __forceinline__ uint32_t smem_to_u32(const void* p) {
    uint32_t a;
    asm("{ .reg .u64 t; cvta.to.shared.u64 t, %1; cvt.u32.u64 %0, t; }" : "=r"(a) : "l"(p));
    return a;
}
__device__ __forceinline__ unsigned long long lds64(uint32_t addr) {
    unsigned long long v;
    asm volatile("ld.shared.b64 %0, [%1];" : "=l"(v) : "r"(addr));
    return v;
}
#define FMA2(d, a, b) \
    asm("fma.rn.f32x2 %0, %1, %2, %0;" : "+l"(d) : "l"(a), "l"(b))
// two 8-byte stores: every address r*136 + q*16 (+8) is 8-aligned
#define STS64X2(sa, v) do { \
    asm volatile("st.shared.v2.b32 [%0], {%1,%2};" \
                 :: "r"(sa), "r"((v).x), "r"((v).y) : "memory"); \
    asm volatile("st.shared.v2.b32 [%0+8], {%1,%2};" \
                 :: "r"(sa), "r"((v).z), "r"((v).w) : "memory"); \
} while (0)

__global__ void dummy_kernel() {}   // 2 leading dummies align ncu launch #6 on pair kernel

__global__ void prep_kernel(const int* __restrict__ cls32) {
    int t = threadIdx.x;
    if (t < NB2) { g_cnt[t] = 0.0f; g_frc[t] = 0.0f; }
    if (t < 32) {
        int v = cls32[2 * t + 1];    // int64 LE: odd words zero (classes 0..31)
        unsigned bal = __ballot_sync(0xffffffffu, v != 0);
        if (t == 0) g_is64 = (bal == 0) ? 1 : 0;
    }
}

__global__ __launch_bounds__(THREADS, 2)
void pair_hist_kernel(const float* __restrict__ F, const void* __restrict__ cls_raw) {
    const int bj = blockIdx.x;   // 0..63  (64-col tiles)
    const int bi = blockIdx.y;   // 0..31  (128-row tiles)
    if (bj < 2 * bi) return;     // tile entirely below diagonal

    __shared__ __align__(16) float As[TM * KST];
    __shared__ __align__(16) float Bs[TN * KST];
    __shared__ unsigned long long whist[NHCOPY][NB2];
    __shared__ int clsA[TM], clsB[TN];

    const int t    = threadIdx.x;
    const int tx   = t & 15;     // n direction (cols, 4 per thread)
    const int ty   = t >> 4;     // m direction (rows, 8 per thread)
    const int wid  = t >> 5;
    const int lane = t & 31;

    for (int i = t; i < NHCOPY * NB2; i += THREADS) (&whist[0][0])[i] = 0ULL;

    if (t < TM) {
        int va;
        if (g_is64) va = (int)((const long long*)cls_raw)[bi * TM + t];
        else        va = ((const int*)cls_raw)[bi * TM + t];
        clsA[t] = va;
    }
    if (t < TN) {
        int vb;
        if (g_is64) vb = (int)((const long long*)cls_raw)[bj * TN + t];
        else        vb = ((const int*)cls_raw)[bj * TN + t];
        clsB[t] = vb;
    }

    const uint32_t sA = smem_to_u32(As);
    const uint32_t sB = smem_to_u32(Bs);
    const uint4* Arow = reinterpret_cast<const uint4*>(F + (size_t)bi * TM * D);
    const uint4* Brow = reinterpret_cast<const uint4*>(F + (size_t)bj * TN * D);
    const int D4 = D / 4;   // row length in uint4

    unsigned long long acc[8][4];
#pragma unroll
    for (int m = 0; m < 8; m++)
#pragma unroll
        for (int n = 0; n < 4; n++) acc[m][n] = 0ULL;

    for (int kc4 = 0; kc4 < D4; kc4 += KC / 4) {
        __syncthreads();
        // A: 128 rows x 8 uint4 = 1024 ; B: 64 x 8 = 512
#pragma unroll
        for (int it = 0; it < 4; it++) {
            int l = it * THREADS + t;
            int r = l >> 3, q = l & 7;
            uint4 v = Arow[r * D4 + kc4 + q];
            STS64X2(sA + (uint32_t)(r * KST + q * 4) * 4u, v);
        }
#pragma unroll
        for (int it = 0; it < 2; it++) {
            int l = it * THREADS + t;
            int r = l >> 3, q = l & 7;
            uint4 v = Brow[r * D4 + kc4 + q];
            STS64X2(sB + (uint32_t)(r * KST + q * 4) * 4u, v);
        }
        __syncthreads();

        // 16 packed k-steps (2 fp32 k per step, packed over k-parity)
#pragma unroll
        for (int kk = 0; kk < KC / 2; kk++) {
            unsigned long long a2[8], b2[4];
#pragma unroll
            for (int m = 0; m < 8; m++)
                a2[m] = lds64(sA + (uint32_t)((ty + 16 * m) * KST + 2 * kk) * 4u);
#pragma unroll
            for (int n = 0; n < 4; n++)
                b2[n] = lds64(sB + (uint32_t)((tx + 16 * n) * KST + 2 * kk) * 4u);
#pragma unroll
            for (int m = 0; m < 8; m++)
#pragma unroll
                for (int n = 0; n < 4; n++)
                    FMA2(acc[m][n], a2[m], b2[n]);
        }
    }

    // ---- warp-aggregated binning ----
    unsigned long long* hw = whist[wid & (NHCOPY - 1)];
    const int dj = bj * TN - bi * TM;   // valid iff jl + dj > il
#pragma unroll
    for (int m = 0; m < 8; m++) {
        const int il = ty + 16 * m;
        const int ci = clsA[il];
#pragma unroll
        for (int n = 0; n < 4; n++) {
            const int jl = tx + 16 * n;
            const bool valid = (jl + dj) > il;
            float lo, hi;
            asm("mov.b64 {%0, %1}, %2;" : "=f"(lo), "=f"(hi) : "l"(acc[m][n]));
            float s = lo + hi;
            float posf = fmaf(s, 50.0f, 50.0f);     // (s+1)/step, step = 2/100
            int idx = (int)floorf(posf);
            idx = max(0, min(idx, NBINS - 1));
            float frac = posf - (float)idx;
            frac = fminf(fmaxf(frac, 0.0f), 1.0f);
            int key = idx + ((ci == clsB[jl]) ? 0 : NBINS);
            unsigned q = __float2uint_rn(frac * QSCALE);
            unsigned act = __ballot_sync(0xffffffffu, valid);
            if (valid) {
                unsigned grp = __match_any_sync(act, key);
                unsigned qs  = __reduce_add_sync(grp, q);
                if (lane == __ffs(grp) - 1) {
                    unsigned long long v =
                        ((unsigned long long)__popc(grp) << 40) | (unsigned long long)qs;
                    atomicAdd(&hw[key], v);
                }
            }
        }
    }

    __syncthreads();
    for (int i = t; i < NB2; i += THREADS) {
        unsigned long long s = 0ULL;
#pragma unroll
        for (int w = 0; w < NHCOPY; w++) s += whist[w][i];
        if (s != 0ULL) {
            atomicAdd(&g_cnt[i], (float)(unsigned)(s >> 40));
            atomicAdd(&g_frc[i], (float)(unsigned long long)(s & QMASK) * (1.0f / QSCALE));
        }
    }
}

__global__ void finalize_kernel(float* out) {
    __shared__ float hp[NBINS], hn[NBINS];
    int t = threadIdx.x;
    if (t < NB2) {
        int b = (t < NBINS) ? t : (t - NBINS);
        float h = g_cnt[t];
        if (b < NBINS - 1) h -= g_frc[t];
        if (b > 0)         h += g_frc[t - 1];
        if (t < NBINS) hp[b] = h; else hn[b] = h;
    }
    __syncthreads();
    if (t == 0) {
        double Sp = 0.0, Sn = 0.0;
#pragma unroll 4
        for (int i = 0; i < NBINS; i++) { Sp += (double)hp[i]; Sn += (double)hn[i]; }
        if (Sp <= 0.0) Sp = 1.0;
        if (Sn <= 0.0) Sn = 1.0;
        double cdf = 0.0, loss = 0.0;
#pragma unroll 4
        for (int j = 0; j < NBINS; j++) {
            cdf  += (double)hp[j];
            loss += (double)hn[j] * cdf;
        }
        out[0] = (float)(loss / (Sp * Sn));
    }
}

extern "C" void kernel_launch(void* const* d_in, const int* in_sizes, int n_in,
                              void* d_out, int out_size) {
    const float* F  = (const float*)d_in[0];
    const void* cls = d_in[1];
    (void)in_sizes; (void)n_in; (void)out_size;

    dummy_kernel<<<1, 32>>>();
    dummy_kernel<<<1, 32>>>();
    prep_kernel<<<1, 256>>>((const int*)cls);
    dim3 grid(NF / TN, NF / TM);   // 64 x 32
    pair_hist_kernel<<<grid, THREADS>>>(F, cls);
    finalize_kernel<<<1, 256>>>((float*)d_out);
}